// round 8
// baseline (speedup 1.0000x reference)
#include <cuda_runtime.h>
#include <cuda_fp16.h>
#include <cstdint>
#include <cstddef>

// Problem: B=16, T=960, D=1024, W=10
#define DDIM  1024
#define WWIN  10
#define MTOT  15360          // B*T
#define KCONV 3072           // 3*D

static constexpr size_t XSZ = (size_t)MTOT * DDIM;
static constexpr size_t WSZ = (size_t)DDIM * KCONV;
static constexpr size_t GSZ = (size_t)DDIM * DDIM;

// Device scratch (allocation-free rules)
__device__ __half  g_x1[XSZ];      // x fp16, [m][c]
__device__ __half  g_w1[WSZ];      // conv w fp16, [n][k=s*1024+c]
__device__ __half  g_g1[GSZ];      // gate w fp16, [e][d]
__device__ __half  g_c1[XSZ];      // cnn fp16, [m][d]

// ------------------------------------------------------------------ PTX helpers
__device__ __forceinline__ uint32_t smem_u32(const void* p) {
    uint32_t a;
    asm("{ .reg .u64 t; cvta.to.shared.u64 t, %1; cvt.u32.u64 %0, t; }" : "=r"(a) : "l"(p));
    return a;
}
__device__ __forceinline__ void cp16(uint32_t dst, const void* src, uint32_t sz) {
    asm volatile("cp.async.cg.shared.global [%0], [%1], 16, %2;"
                 :: "r"(dst), "l"(src), "r"(sz) : "memory");
}
__device__ __forceinline__ void ldsm4(uint32_t* r, uint32_t addr) {
    asm volatile("ldmatrix.sync.aligned.m8n8.x4.shared.b16 {%0,%1,%2,%3}, [%4];"
                 : "=r"(r[0]), "=r"(r[1]), "=r"(r[2]), "=r"(r[3]) : "r"(addr));
}
__device__ __forceinline__ void mma16816(float* d, const uint32_t* a, const uint32_t* b) {
    asm volatile("mma.sync.aligned.m16n8k16.row.col.f32.f16.f16.f32 "
                 "{%0,%1,%2,%3}, {%4,%5,%6,%7}, {%8,%9}, {%0,%1,%2,%3};"
                 : "+f"(d[0]), "+f"(d[1]), "+f"(d[2]), "+f"(d[3])
                 : "r"(a[0]), "r"(a[1]), "r"(a[2]), "r"(a[3]), "r"(b[0]), "r"(b[1]));
}
__device__ __forceinline__ uint32_t pack_h2(float a, float b) {
    return (uint32_t)__half_as_ushort(__float2half_rn(a)) |
           ((uint32_t)__half_as_ushort(__float2half_rn(b)) << 16);
}
__device__ __forceinline__ void mbar_init(uint32_t a, uint32_t cnt) {
    asm volatile("mbarrier.init.shared.b64 [%0], %1;" :: "r"(a), "r"(cnt) : "memory");
}
__device__ __forceinline__ void mbar_wait(uint32_t a, uint32_t ph) {
    uint32_t done = 0;
    while (!done) {
        asm volatile(
            "{\n\t.reg .pred p;\n\t"
            "mbarrier.try_wait.parity.acquire.cta.shared::cta.b64 p, [%1], %2, 0x989680;\n\t"
            "selp.b32 %0, 1, 0, p;\n\t}"
            : "=r"(done) : "r"(a), "r"(ph) : "memory");
    }
}
__device__ __forceinline__ void mbar_arrive(uint32_t a) {
    asm volatile("mbarrier.arrive.shared.b64 _, [%0];" :: "r"(a) : "memory");
}
__device__ __forceinline__ void cp_arrive_noinc(uint32_t a) {
    asm volatile("cp.async.mbarrier.arrive.noinc.shared.b64 [%0];" :: "r"(a) : "memory");
}

// ------------------------------------------------------------------ preprocessing
__global__ void k_split_x(const float* __restrict__ x) {
    size_t i = ((size_t)blockIdx.x * 256 + threadIdx.x) * 4;
    float4 v = *reinterpret_cast<const float4*>(x + i);
    uint2 uh;
    uh.x = pack_h2(v.x, v.y); uh.y = pack_h2(v.z, v.w);
    *reinterpret_cast<uint2*>(g_x1 + i) = uh;
}
__global__ void k_split_convw(const float* __restrict__ w) {
    size_t i = (size_t)blockIdx.x * 256 + threadIdx.x;   // over WSZ, out layout [n][s*1024+c]
    int n = (int)(i / KCONV);
    int k = (int)(i - (size_t)n * KCONV);
    int s = k >> 10, c = k & (DDIM - 1);
    g_w1[i] = __float2half_rn(w[(size_t)n * KCONV + c * 3 + s]);
}
__global__ void k_split_gatew(const float* __restrict__ gw) {
    size_t i = ((size_t)blockIdx.x * 256 + threadIdx.x) * 4;
    float4 v = *reinterpret_cast<const float4*>(gw + i);
    uint2 uh;
    uh.x = pack_h2(v.x, v.y); uh.y = pack_h2(v.z, v.w);
    *reinterpret_cast<uint2*>(g_g1 + i) = uh;
}

// ------------------------------------------------------------------ main GEMM
// CTA 128x128, BK=64 fp16, 3-stage ring [A 16KB | B 16KB] = 96KB, occ 2.
// Warp-specialized: warps 0-7 = MMA consumers (4(M) x 2(N), tile 32x64),
// warp 8 = cp.async producer. mbarrier full/empty per stage, no __syncthreads
// in the main loop.
static constexpr int PL_A = 0, PL_B = 16384;
static constexpr int STSZ = 32768;
static constexpr int MB_OFF = 3 * STSZ;          // full[3] then empty[3], 8B each
static constexpr int SMEM_SZ = 3 * STSZ + 64;    // 98368 B

template <int CHUNKS, bool IS_CONV>
__global__ __launch_bounds__(288, 2)
void k_mma(const float* __restrict__ bias, float* __restrict__ out) {
    extern __shared__ char smem[];
    const uint32_t sb = smem_u32(smem);
    const uint32_t mbF = sb + MB_OFF;        // full barriers, 3 x 8B
    const uint32_t mbE = sb + MB_OFF + 24;   // empty barriers, 3 x 8B

    const int tid = threadIdx.x;
    const int lane = tid & 31, w = tid >> 5;
    const int m0 = blockIdx.y * 128, n0 = blockIdx.x * 128;

    if (tid == 0) {
#pragma unroll
        for (int s = 0; s < 3; ++s) {
            mbar_init(mbF + s * 8, 32);   // 32 producer threads, deferred arrives
            mbar_init(mbE + s * 8, 8);    // 8 consumer warps, lane-0 arrives
        }
    }
    __syncthreads();

    if (w == 8) {
        // ---------------- producer warp ----------------
        // each lane owns 4 rows: lane*4 + j
        int rows[4], amws[4];
#pragma unroll
        for (int j = 0; j < 4; ++j) {
            rows[j] = lane * 4 + j;
            amws[j] = (m0 + rows[j]) % WWIN;
        }
        for (int i = 0; i < CHUNKS; ++i) {
            const int st = i % 3;
            const int rnd = i / 3;
            if (i >= 3) mbar_wait(mbE + st * 8, (rnd - 1) & 1);
            const uint32_t base = sb + st * STSZ;
#pragma unroll
            for (int j = 0; j < 4; ++j) {
                const int r = rows[j];
                const __half* Ap;
                const __half* Bp;
                uint32_t asz = 16;
                if (IS_CONV) {
                    const int s = i >> 4, dt = s - 1, kc = (i & 15) << 6;
                    const bool valid = ((unsigned)(amws[j] + dt)) < (unsigned)WWIN;
                    asz = valid ? 16u : 0u;
                    Ap = g_x1 + (size_t)(m0 + r + (valid ? dt : 0)) * DDIM + kc;
                    Bp = g_w1 + (size_t)(n0 + r) * KCONV + (i << 6);
                } else {
                    Ap = g_c1 + (size_t)(m0 + r) * DDIM + (i << 6);
                    Bp = g_g1 + (size_t)(n0 + r) * DDIM + (i << 6);
                }
                const uint32_t rowbase = base + r * 128;
#pragma unroll
                for (int cc = 0; cc < 8; ++cc) {
                    const uint32_t swz = (uint32_t)((cc ^ (r & 7)) * 16);
                    cp16(rowbase + PL_A + swz, Ap + cc * 8, asz);
                    cp16(rowbase + PL_B + swz, Bp + cc * 8, 16);
                }
            }
            cp_arrive_noinc(mbF + st * 8);
        }
        return;
    }

    // ---------------- consumer warps (0-7) ----------------
    const int wm = w >> 1, wn = w & 1;          // 4(M) x 2(N)
    const int li = lane & 7, lg = lane >> 3;

    float acc[2][8][4];
#pragma unroll
    for (int i = 0; i < 2; ++i)
#pragma unroll
        for (int j = 0; j < 8; ++j)
#pragma unroll
            for (int q = 0; q < 4; ++q) acc[i][j][q] = 0.f;

    for (int i = 0; i < CHUNKS; ++i) {
        const int st = i % 3;
        mbar_wait(mbF + st * 8, (i / 3) & 1);
        const uint32_t bb = sb + st * STSZ;
#pragma unroll
        for (int ks = 0; ks < 4; ++ks) {
            uint32_t Bf[4][4];
#pragma unroll
            for (int nt2 = 0; nt2 < 4; ++nt2) {
                const int br = wn * 64 + nt2 * 16 + li + (lg >> 1) * 8;
                const uint32_t cx = (uint32_t)((ks * 2 + (lg & 1)) ^ li);
                ldsm4(Bf[nt2], bb + PL_B + br * 128 + cx * 16);
            }
#pragma unroll
            for (int mt = 0; mt < 2; ++mt) {
                const int ar = wm * 32 + mt * 16 + li + (lg & 1) * 8;
                const uint32_t cx = (uint32_t)((ks * 2 + (lg >> 1)) ^ li);
                uint32_t Af[4];
                ldsm4(Af, bb + PL_A + ar * 128 + cx * 16);
#pragma unroll
                for (int nt = 0; nt < 8; ++nt) {
                    const uint32_t b2[2] = {Bf[nt >> 1][(nt & 1) * 2],
                                            Bf[nt >> 1][(nt & 1) * 2 + 1]};
                    mma16816(acc[mt][nt], Af, b2);
                }
            }
        }
        if (lane == 0) mbar_arrive(mbE + st * 8);
    }

    // ---- epilogue (direct from fragments; cnn kept in fp16 only)
#pragma unroll
    for (int mt = 0; mt < 2; ++mt) {
#pragma unroll
        for (int nt = 0; nt < 8; ++nt) {
            const int gn = n0 + wn * 64 + nt * 8 + (lane & 3) * 2;
            const float b0 = bias[gn], b1 = bias[gn + 1];
#pragma unroll
            for (int hh = 0; hh < 2; ++hh) {
                const int gm = m0 + wm * 32 + mt * 16 + (lane >> 2) + hh * 8;
                float v0 = acc[mt][nt][hh * 2 + 0] + b0;
                float v1 = acc[mt][nt][hh * 2 + 1] + b1;
                const size_t off = (size_t)gm * DDIM + gn;
                if (IS_CONV) {
                    *reinterpret_cast<uint32_t*>(g_c1 + off) = pack_h2(v0, v1);
                } else {
                    const __half2 ch = *reinterpret_cast<const __half2*>(g_c1 + off);
                    const float2 cv = __half22float2(ch);
                    float2 o;
                    o.x = cv.x * (1.f / (1.f + __expf(-v0)));
                    o.y = cv.y * (1.f / (1.f + __expf(-v1)));
                    *reinterpret_cast<float2*>(out + off) = o;
                }
            }
        }
    }
}

// ------------------------------------------------------------------ launch
extern "C" void kernel_launch(void* const* d_in, const int* in_sizes, int n_in,
                              void* d_out, int out_size) {
    const float* x      = (const float*)d_in[0];
    const float* conv_w = (const float*)d_in[1];
    const float* conv_b = (const float*)d_in[2];
    const float* gate_w = (const float*)d_in[3];
    const float* gate_b = (const float*)d_in[4];
    float* out = (float*)d_out;

    cudaFuncSetAttribute(k_mma<48, true>,  cudaFuncAttributeMaxDynamicSharedMemorySize, SMEM_SZ);
    cudaFuncSetAttribute(k_mma<16, false>, cudaFuncAttributeMaxDynamicSharedMemorySize, SMEM_SZ);

    k_split_x<<<(int)(XSZ / 1024), 256>>>(x);
    k_split_convw<<<(int)(WSZ / 256), 256>>>(conv_w);
    k_split_gatew<<<(int)(GSZ / 1024), 256>>>(gate_w);

    dim3 grid(DDIM / 128, MTOT / 128);   // (8, 120)
    k_mma<48, true><<<grid, 288, SMEM_SZ>>>(conv_b, nullptr);
    k_mma<16, false><<<grid, 288, SMEM_SZ>>>(gate_b, out);
}

// round 9
// speedup vs baseline: 1.2770x; 1.2770x over previous
#include <cuda_runtime.h>
#include <cuda_fp16.h>
#include <cstdint>
#include <cstddef>

// Problem: B=16, T=960, D=1024, W=10
#define DDIM  1024
#define WWIN  10
#define MTOT  15360          // B*T
#define KCONV 3072           // 3*D

static constexpr size_t XSZ = (size_t)MTOT * DDIM;
static constexpr size_t WSZ = (size_t)DDIM * KCONV;
static constexpr size_t GSZ = (size_t)DDIM * DDIM;

// Device scratch (allocation-free rules; zero-initialized by CUDA)
__device__ __half  g_x1[XSZ];      // x fp16, [m][c]
__device__ __half  g_w1[WSZ];      // conv w fp16, [n][k=s*1024+c]
__device__ __half  g_g1[GSZ];      // gate w fp16, [e][d]
__device__ __half  g_c1[XSZ];      // cnn fp16, [m][d]
__device__ __align__(128) __half g_zero[64];   // 128B of zeros (masked conv taps)

// ------------------------------------------------------------------ PTX helpers
__device__ __forceinline__ uint32_t smem_u32(const void* p) {
    uint32_t a;
    asm("{ .reg .u64 t; cvta.to.shared.u64 t, %1; cvt.u32.u64 %0, t; }" : "=r"(a) : "l"(p));
    return a;
}
__device__ __forceinline__ void cpbulk(uint32_t dst, const void* src, uint32_t bytes,
                                       uint32_t mbar) {
    asm volatile(
        "cp.async.bulk.shared::cluster.global.mbarrier::complete_tx::bytes "
        "[%0], [%1], %2, [%3];"
        :: "r"(dst), "l"(src), "r"(bytes), "r"(mbar) : "memory");
}
__device__ __forceinline__ void mbar_init(uint32_t a, uint32_t cnt) {
    asm volatile("mbarrier.init.shared.b64 [%0], %1;" :: "r"(a), "r"(cnt) : "memory");
}
__device__ __forceinline__ void mbar_expect_tx(uint32_t a, uint32_t tx) {
    asm volatile("mbarrier.arrive.expect_tx.shared.b64 _, [%0], %1;"
                 :: "r"(a), "r"(tx) : "memory");
}
__device__ __forceinline__ void mbar_wait(uint32_t a, uint32_t ph) {
    uint32_t done = 0;
    while (!done) {
        asm volatile(
            "{\n\t.reg .pred p;\n\t"
            "mbarrier.try_wait.parity.acquire.cta.shared::cta.b64 p, [%1], %2, 0x989680;\n\t"
            "selp.b32 %0, 1, 0, p;\n\t}"
            : "=r"(done) : "r"(a), "r"(ph) : "memory");
    }
}
__device__ __forceinline__ void mbar_arrive(uint32_t a) {
    asm volatile("mbarrier.arrive.shared.b64 _, [%0];" :: "r"(a) : "memory");
}
__device__ __forceinline__ void ldsm4(uint32_t* r, uint32_t addr) {
    asm volatile("ldmatrix.sync.aligned.m8n8.x4.shared.b16 {%0,%1,%2,%3}, [%4];"
                 : "=r"(r[0]), "=r"(r[1]), "=r"(r[2]), "=r"(r[3]) : "r"(addr));
}
__device__ __forceinline__ void mma16816(float* d, const uint32_t* a, const uint32_t* b) {
    asm volatile("mma.sync.aligned.m16n8k16.row.col.f32.f16.f16.f32 "
                 "{%0,%1,%2,%3}, {%4,%5,%6,%7}, {%8,%9}, {%0,%1,%2,%3};"
                 : "+f"(d[0]), "+f"(d[1]), "+f"(d[2]), "+f"(d[3])
                 : "r"(a[0]), "r"(a[1]), "r"(a[2]), "r"(a[3]), "r"(b[0]), "r"(b[1]));
}
__device__ __forceinline__ uint32_t pack_h2(float a, float b) {
    return (uint32_t)__half_as_ushort(__float2half_rn(a)) |
           ((uint32_t)__half_as_ushort(__float2half_rn(b)) << 16);
}

// ------------------------------------------------------------------ preprocessing (merged)
static constexpr int PB_X = (int)(XSZ / 1024);           // 15360 blocks, 4 elem/thread
static constexpr int PB_W = (int)(WSZ / 256);            // 12288 blocks, 1 elem/thread
static constexpr int PB_G = (int)(GSZ / 1024);           // 1024 blocks, 4 elem/thread
__global__ void k_prep(const float* __restrict__ x, const float* __restrict__ cw,
                       const float* __restrict__ gw) {
    const int b = blockIdx.x;
    if (b < PB_X) {
        size_t i = ((size_t)b * 256 + threadIdx.x) * 4;
        float4 v = *reinterpret_cast<const float4*>(x + i);
        uint2 u; u.x = pack_h2(v.x, v.y); u.y = pack_h2(v.z, v.w);
        *reinterpret_cast<uint2*>(g_x1 + i) = u;
    } else if (b < PB_X + PB_W) {
        size_t i = (size_t)(b - PB_X) * 256 + threadIdx.x;   // [n][k=s*1024+c]
        int n = (int)(i / KCONV);
        int k = (int)(i - (size_t)n * KCONV);
        int s = k >> 10, c = k & (DDIM - 1);
        g_w1[i] = __float2half_rn(cw[(size_t)n * KCONV + c * 3 + s]);
    } else {
        size_t i = ((size_t)(b - PB_X - PB_W) * 256 + threadIdx.x) * 4;
        float4 v = *reinterpret_cast<const float4*>(gw + i);
        uint2 u; u.x = pack_h2(v.x, v.y); u.y = pack_h2(v.z, v.w);
        *reinterpret_cast<uint2*>(g_g1 + i) = u;
    }
}

// ------------------------------------------------------------------ main GEMM
// CTA 128x128, BK=64 fp16. Rows at 144B pitch (128B data + 16B pad) ->
// bank-conflict-free ldsm with NO swizzle, enabling cp.async.bulk row loads.
// 3-stage ring, occ 2, mbarrier full/empty, no __syncthreads in main loop.
// 8 warps 4(M) x 2(N), warp tile 32x64.
static constexpr int ROWB = 144;
static constexpr int PL_A = 0, PL_B = 128 * ROWB;        // 18432
static constexpr int STSZ = 2 * 128 * ROWB;              // 36864
static constexpr int MB_OFF = 3 * STSZ;                  // 110592
static constexpr int SMEM_SZ = MB_OFF + 64;              // 110656

template <int CHUNKS, bool IS_CONV>
__global__ __launch_bounds__(256, 2)
void k_mma(const float* __restrict__ bias, float* __restrict__ out) {
    extern __shared__ char smem[];
    const uint32_t sb = smem_u32(smem);
    const uint32_t mbF = sb + MB_OFF;        // full[3], 8B each
    const uint32_t mbE = sb + MB_OFF + 24;   // empty[3], 8B each

    const int tid = threadIdx.x;
    const int lane = tid & 31, w = tid >> 5;
    const int m0 = blockIdx.y * 128, n0 = blockIdx.x * 128;
    const int wm = w >> 1, wn = w & 1;       // warp grid 4(M) x 2(N)
    const int li = lane & 7, lg = lane >> 3;

    if (tid == 0) {
#pragma unroll
        for (int s = 0; s < 3; ++s) {
            mbar_init(mbF + s * 8, 256);     // per-thread expect_tx arrivals
            mbar_init(mbE + s * 8, 8);       // lane-0 of each warp
        }
    }
    __syncthreads();

    // Each thread owns ONE row copy per chunk: tid<128 -> A row tid, else B row.
    const bool isA = (tid < 128);
    const int row = isA ? tid : (tid - 128);
    const int amw = (m0 + row) % WWIN;       // conv window pos (A rows only)

    auto load_stage = [&](int c, int st) {
        const uint32_t base = sb + st * STSZ;
        const void* src;
        if (isA) {
            if (IS_CONV) {
                const int s = c >> 4, dt = s - 1, kc = (c & 15) << 6;
                const bool valid = ((unsigned)(amw + dt)) < (unsigned)WWIN;
                src = valid ? (const void*)(g_x1 + (size_t)(m0 + row + dt) * DDIM + kc)
                            : (const void*)g_zero;
            } else {
                src = g_c1 + (size_t)(m0 + row) * DDIM + (c << 6);
            }
        } else {
            src = IS_CONV ? (const void*)(g_w1 + (size_t)(n0 + row) * KCONV + (c << 6))
                          : (const void*)(g_g1 + (size_t)(n0 + row) * DDIM + (c << 6));
        }
        const uint32_t dst = base + (isA ? PL_A : PL_B) + row * ROWB;
        mbar_expect_tx(mbF + st * 8, 128);
        cpbulk(dst, src, 128, mbF + st * 8);
    };

    // Prologue: stages 0..2
#pragma unroll
    for (int p = 0; p < 3; ++p)
        if (p < CHUNKS) load_stage(p, p);

    float acc[2][8][4];
#pragma unroll
    for (int i = 0; i < 2; ++i)
#pragma unroll
        for (int j = 0; j < 8; ++j)
#pragma unroll
            for (int q = 0; q < 4; ++q) acc[i][j][q] = 0.f;

    for (int i = 0; i < CHUNKS; ++i) {
        const int st = i % 3;
        const uint32_t ph = (uint32_t)((i / 3) & 1);
        mbar_wait(mbF + st * 8, ph);
        const uint32_t bb = sb + st * STSZ;

#pragma unroll
        for (int ks = 0; ks < 4; ++ks) {
            uint32_t Bf[4][4];
#pragma unroll
            for (int nt2 = 0; nt2 < 4; ++nt2) {
                const int br = wn * 64 + nt2 * 16 + li + (lg >> 1) * 8;
                ldsm4(Bf[nt2], bb + PL_B + br * ROWB + (ks * 2 + (lg & 1)) * 16);
            }
#pragma unroll
            for (int mt = 0; mt < 2; ++mt) {
                const int ar = wm * 32 + mt * 16 + li + (lg & 1) * 8;
                uint32_t Af[4];
                ldsm4(Af, bb + PL_A + ar * ROWB + (ks * 2 + (lg >> 1)) * 16);
#pragma unroll
                for (int nt = 0; nt < 8; ++nt) {
                    const uint32_t b2[2] = {Bf[nt >> 1][(nt & 1) * 2],
                                            Bf[nt >> 1][(nt & 1) * 2 + 1]};
                    mma16816(acc[mt][nt], Af, b2);
                }
            }
        }
        if (lane == 0) mbar_arrive(mbE + st * 8);
        if (i + 3 < CHUNKS) {
            mbar_wait(mbE + st * 8, ph);     // all 8 warps done with round i of st
            load_stage(i + 3, st);
        }
    }

    // ---- epilogue (direct from fragments; cnn kept in fp16 only)
#pragma unroll
    for (int mt = 0; mt < 2; ++mt) {
#pragma unroll
        for (int nt = 0; nt < 8; ++nt) {
            const int gn = n0 + wn * 64 + nt * 8 + (lane & 3) * 2;
            const float b0 = bias[gn], b1 = bias[gn + 1];
#pragma unroll
            for (int hh = 0; hh < 2; ++hh) {
                const int gm = m0 + wm * 32 + mt * 16 + (lane >> 2) + hh * 8;
                float v0 = acc[mt][nt][hh * 2 + 0] + b0;
                float v1 = acc[mt][nt][hh * 2 + 1] + b1;
                const size_t off = (size_t)gm * DDIM + gn;
                if (IS_CONV) {
                    *reinterpret_cast<uint32_t*>(g_c1 + off) = pack_h2(v0, v1);
                } else {
                    const __half2 ch = *reinterpret_cast<const __half2*>(g_c1 + off);
                    const float2 cv = __half22float2(ch);
                    float2 o;
                    o.x = cv.x * (1.f / (1.f + __expf(-v0)));
                    o.y = cv.y * (1.f / (1.f + __expf(-v1)));
                    *reinterpret_cast<float2*>(out + off) = o;
                }
            }
        }
    }
}

// ------------------------------------------------------------------ launch
extern "C" void kernel_launch(void* const* d_in, const int* in_sizes, int n_in,
                              void* d_out, int out_size) {
    const float* x      = (const float*)d_in[0];
    const float* conv_w = (const float*)d_in[1];
    const float* conv_b = (const float*)d_in[2];
    const float* gate_w = (const float*)d_in[3];
    const float* gate_b = (const float*)d_in[4];
    float* out = (float*)d_out;

    cudaFuncSetAttribute(k_mma<48, true>,  cudaFuncAttributeMaxDynamicSharedMemorySize, SMEM_SZ);
    cudaFuncSetAttribute(k_mma<16, false>, cudaFuncAttributeMaxDynamicSharedMemorySize, SMEM_SZ);

    k_prep<<<PB_X + PB_W + PB_G, 256>>>(x, conv_w, gate_w);

    dim3 grid(DDIM / 128, MTOT / 128);   // (8, 120)
    k_mma<48, true><<<grid, 256, SMEM_SZ>>>(conv_b, nullptr);
    k_mma<16, false><<<grid, 256, SMEM_SZ>>>(gate_b, out);
}

// round 10
// speedup vs baseline: 1.2772x; 1.0002x over previous
#include <cuda_runtime.h>
#include <cuda_fp16.h>
#include <cstdint>
#include <cstddef>

// Problem: B=16, T=960, D=1024, W=10
#define DDIM  1024
#define WWIN  10
#define MTOT  15360          // B*T
#define KCONV 3072           // 3*D

static constexpr size_t XSZ = (size_t)MTOT * DDIM;
static constexpr size_t WSZ = (size_t)DDIM * KCONV;
static constexpr size_t GSZ = (size_t)DDIM * DDIM;

// Device scratch (allocation-free rules; zero-initialized by CUDA)
__device__ __half  g_x1[XSZ];      // x fp16, [m][c]
__device__ __half  g_w1[WSZ];      // conv w fp16, [n][k=s*1024+c]
__device__ __half  g_g1[GSZ];      // gate w fp16, [e][d]
__device__ __half  g_c1[XSZ];      // cnn fp16, [m][d]
__device__ __align__(128) __half g_zero[64];   // 128B of zeros (masked conv taps)

// ------------------------------------------------------------------ PTX helpers
__device__ __forceinline__ uint32_t smem_u32(const void* p) {
    uint32_t a;
    asm("{ .reg .u64 t; cvta.to.shared.u64 t, %1; cvt.u32.u64 %0, t; }" : "=r"(a) : "l"(p));
    return a;
}
__device__ __forceinline__ void cpbulk(uint32_t dst, const void* src, uint32_t bytes,
                                       uint32_t mbar) {
    asm volatile(
        "cp.async.bulk.shared::cluster.global.mbarrier::complete_tx::bytes "
        "[%0], [%1], %2, [%3];"
        :: "r"(dst), "l"(src), "r"(bytes), "r"(mbar) : "memory");
}
__device__ __forceinline__ void mbar_init(uint32_t a, uint32_t cnt) {
    asm volatile("mbarrier.init.shared.b64 [%0], %1;" :: "r"(a), "r"(cnt) : "memory");
}
__device__ __forceinline__ void mbar_expect_tx(uint32_t a, uint32_t tx) {
    asm volatile("mbarrier.arrive.expect_tx.shared.b64 _, [%0], %1;"
                 :: "r"(a), "r"(tx) : "memory");
}
__device__ __forceinline__ void mbar_wait(uint32_t a, uint32_t ph) {
    uint32_t done = 0;
    while (!done) {
        asm volatile(
            "{\n\t.reg .pred p;\n\t"
            "mbarrier.try_wait.parity.acquire.cta.shared::cta.b64 p, [%1], %2, 0x989680;\n\t"
            "selp.b32 %0, 1, 0, p;\n\t}"
            : "=r"(done) : "r"(a), "r"(ph) : "memory");
    }
}
__device__ __forceinline__ void mbar_arrive(uint32_t a) {
    asm volatile("mbarrier.arrive.shared.b64 _, [%0];" :: "r"(a) : "memory");
}
__device__ __forceinline__ void ldsm4(uint32_t* r, uint32_t addr) {
    asm volatile("ldmatrix.sync.aligned.m8n8.x4.shared.b16 {%0,%1,%2,%3}, [%4];"
                 : "=r"(r[0]), "=r"(r[1]), "=r"(r[2]), "=r"(r[3]) : "r"(addr));
}
__device__ __forceinline__ void mma16816(float* d, const uint32_t* a, const uint32_t* b) {
    asm volatile("mma.sync.aligned.m16n8k16.row.col.f32.f16.f16.f32 "
                 "{%0,%1,%2,%3}, {%4,%5,%6,%7}, {%8,%9}, {%0,%1,%2,%3};"
                 : "+f"(d[0]), "+f"(d[1]), "+f"(d[2]), "+f"(d[3])
                 : "r"(a[0]), "r"(a[1]), "r"(a[2]), "r"(a[3]), "r"(b[0]), "r"(b[1]));
}
__device__ __forceinline__ uint32_t pack_h2(float a, float b) {
    return (uint32_t)__half_as_ushort(__float2half_rn(a)) |
           ((uint32_t)__half_as_ushort(__float2half_rn(b)) << 16);
}

// ------------------------------------------------------------------ preprocessing (merged)
static constexpr int PB_X = (int)(XSZ / 1024);
static constexpr int PB_W = (int)(WSZ / 256);
static constexpr int PB_G = (int)(GSZ / 1024);
__global__ void k_prep(const float* __restrict__ x, const float* __restrict__ cw,
                       const float* __restrict__ gw) {
    const int b = blockIdx.x;
    if (b < PB_X) {
        size_t i = ((size_t)b * 256 + threadIdx.x) * 4;
        float4 v = *reinterpret_cast<const float4*>(x + i);
        uint2 u; u.x = pack_h2(v.x, v.y); u.y = pack_h2(v.z, v.w);
        *reinterpret_cast<uint2*>(g_x1 + i) = u;
    } else if (b < PB_X + PB_W) {
        size_t i = (size_t)(b - PB_X) * 256 + threadIdx.x;   // [n][k=s*1024+c]
        int n = (int)(i / KCONV);
        int k = (int)(i - (size_t)n * KCONV);
        int s = k >> 10, c = k & (DDIM - 1);
        g_w1[i] = __float2half_rn(cw[(size_t)n * KCONV + c * 3 + s]);
    } else {
        size_t i = ((size_t)(b - PB_X - PB_W) * 256 + threadIdx.x) * 4;
        float4 v = *reinterpret_cast<const float4*>(gw + i);
        uint2 u; u.x = pack_h2(v.x, v.y); u.y = pack_h2(v.z, v.w);
        *reinterpret_cast<uint2*>(g_g1 + i) = u;
    }
}

// ------------------------------------------------------------------ main GEMM
// CTA 128x128, BK=64 fp16, rows at 144B pitch (conflict-free ldsm, no swizzle),
// cp.async.bulk row loads, 3-stage mbarrier ring, occ 2.
// Flat k16-slice pipeline: ldsm of slice s+1 (incl. next chunk) overlaps MMAs
// of slice s; arrive-empty fires before the last MMA block of each chunk.
static constexpr int ROWB = 144;
static constexpr int PL_A = 0, PL_B = 128 * ROWB;        // 18432
static constexpr int STSZ = 2 * 128 * ROWB;              // 36864
static constexpr int MB_OFF = 3 * STSZ;                  // 110592
static constexpr int SMEM_SZ = MB_OFF + 64;              // 110656

template <int CHUNKS, bool IS_CONV>
__global__ __launch_bounds__(256, 2)
void k_mma(const float* __restrict__ bias, float* __restrict__ out) {
    extern __shared__ char smem[];
    const uint32_t sb = smem_u32(smem);
    const uint32_t mbF = sb + MB_OFF;        // full[3]
    const uint32_t mbE = sb + MB_OFF + 24;   // empty[3]

    const int tid = threadIdx.x;
    const int lane = tid & 31, w = tid >> 5;
    const int m0 = blockIdx.y * 128, n0 = blockIdx.x * 128;
    const int wm = w >> 1, wn = w & 1;       // warp grid 4(M) x 2(N)
    const int li = lane & 7, lg = lane >> 3;

    if (tid == 0) {
#pragma unroll
        for (int s = 0; s < 3; ++s) {
            mbar_init(mbF + s * 8, 256);     // per-thread expect_tx arrivals
            mbar_init(mbE + s * 8, 8);       // lane-0 of each warp
        }
    }
    __syncthreads();

    // Each thread owns ONE row copy per chunk: tid<128 -> A row tid, else B row.
    const bool isA = (tid < 128);
    const int row = isA ? tid : (tid - 128);
    const int amw = (m0 + row) % WWIN;

    auto load_stage = [&](int c, int st) {
        const uint32_t base = sb + st * STSZ;
        const void* src;
        if (isA) {
            if (IS_CONV) {
                const int s = c >> 4, dt = s - 1, kc = (c & 15) << 6;
                const bool valid = ((unsigned)(amw + dt)) < (unsigned)WWIN;
                src = valid ? (const void*)(g_x1 + (size_t)(m0 + row + dt) * DDIM + kc)
                            : (const void*)g_zero;
            } else {
                src = g_c1 + (size_t)(m0 + row) * DDIM + (c << 6);
            }
        } else {
            src = IS_CONV ? (const void*)(g_w1 + (size_t)(n0 + row) * KCONV + (c << 6))
                          : (const void*)(g_g1 + (size_t)(n0 + row) * DDIM + (c << 6));
        }
        const uint32_t dst = base + (isA ? PL_A : PL_B) + row * ROWB;
        mbar_expect_tx(mbF + st * 8, 128);
        cpbulk(dst, src, 128, mbF + st * 8);
    };

    // Prologue: stages 0..2
#pragma unroll
    for (int p = 0; p < 3; ++p)
        if (p < CHUNKS) load_stage(p, p);

    float acc[2][8][4];
#pragma unroll
    for (int i = 0; i < 2; ++i)
#pragma unroll
        for (int j = 0; j < 8; ++j)
#pragma unroll
            for (int q = 0; q < 4; ++q) acc[i][j][q] = 0.f;

    uint32_t Bf[2][4][4];
    uint32_t Af[2][2][4];

    auto ldB = [&](uint32_t bb, int ks, int fb) {
#pragma unroll
        for (int nt2 = 0; nt2 < 4; ++nt2) {
            const int br = wn * 64 + nt2 * 16 + li + (lg >> 1) * 8;
            ldsm4(Bf[fb][nt2], bb + PL_B + br * ROWB + (ks * 2 + (lg & 1)) * 16);
        }
    };
    auto ldA = [&](uint32_t bb, int ks, int fb) {
#pragma unroll
        for (int mt = 0; mt < 2; ++mt) {
            const int ar = wm * 32 + mt * 16 + li + (lg & 1) * 8;
            ldsm4(Af[fb][mt], bb + PL_A + ar * ROWB + (ks * 2 + (lg >> 1)) * 16);
        }
    };

    // Pipeline prologue: wait chunk 0, load its first k16 fragments
    mbar_wait(mbF + 0, 0);
    ldB(sb, 0, 0);
    ldA(sb, 0, 0);

    for (int c = 0; c < CHUNKS; ++c) {
        const int st = c % 3;
        const uint32_t bb = sb + st * STSZ;
#pragma unroll
        for (int ks = 0; ks < 4; ++ks) {
            const int cur = ks & 1;
            if (ks < 3) {
                ldB(bb, ks + 1, cur ^ 1);
                ldA(bb, ks + 1, cur ^ 1);
            } else if (c + 1 < CHUNKS) {
                const int st1 = (c + 1) % 3;
                mbar_wait(mbF + st1 * 8, (uint32_t)(((c + 1) / 3) & 1));
                const uint32_t bb1 = sb + st1 * STSZ;
                ldB(bb1, 0, cur ^ 1);
                ldA(bb1, 0, cur ^ 1);
            }
            if (ks == 3 && lane == 0) mbar_arrive(mbE + st * 8);
#pragma unroll
            for (int mt = 0; mt < 2; ++mt) {
#pragma unroll
                for (int nt = 0; nt < 8; ++nt) {
                    const uint32_t b2[2] = {Bf[cur][nt >> 1][(nt & 1) * 2],
                                            Bf[cur][nt >> 1][(nt & 1) * 2 + 1]};
                    mma16816(acc[mt][nt], Af[cur][mt], b2);
                }
            }
            if (ks == 3 && c + 3 < CHUNKS) {
                mbar_wait(mbE + st * 8, (uint32_t)((c / 3) & 1));
                load_stage(c + 3, st);
            }
        }
    }

    // ---- epilogue (direct from fragments; cnn kept in fp16 only)
#pragma unroll
    for (int mt = 0; mt < 2; ++mt) {
#pragma unroll
        for (int nt = 0; nt < 8; ++nt) {
            const int gn = n0 + wn * 64 + nt * 8 + (lane & 3) * 2;
            const float b0 = bias[gn], b1 = bias[gn + 1];
#pragma unroll
            for (int hh = 0; hh < 2; ++hh) {
                const int gm = m0 + wm * 32 + mt * 16 + (lane >> 2) + hh * 8;
                float v0 = acc[mt][nt][hh * 2 + 0] + b0;
                float v1 = acc[mt][nt][hh * 2 + 1] + b1;
                const size_t off = (size_t)gm * DDIM + gn;
                if (IS_CONV) {
                    *reinterpret_cast<uint32_t*>(g_c1 + off) = pack_h2(v0, v1);
                } else {
                    const __half2 ch = *reinterpret_cast<const __half2*>(g_c1 + off);
                    const float2 cv = __half22float2(ch);
                    float2 o;
                    o.x = cv.x * (1.f / (1.f + __expf(-v0)));
                    o.y = cv.y * (1.f / (1.f + __expf(-v1)));
                    *reinterpret_cast<float2*>(out + off) = o;
                }
            }
        }
    }
}

// ------------------------------------------------------------------ launch
extern "C" void kernel_launch(void* const* d_in, const int* in_sizes, int n_in,
                              void* d_out, int out_size) {
    const float* x      = (const float*)d_in[0];
    const float* conv_w = (const float*)d_in[1];
    const float* conv_b = (const float*)d_in[2];
    const float* gate_w = (const float*)d_in[3];
    const float* gate_b = (const float*)d_in[4];
    float* out = (float*)d_out;

    cudaFuncSetAttribute(k_mma<48, true>,  cudaFuncAttributeMaxDynamicSharedMemorySize, SMEM_SZ);
    cudaFuncSetAttribute(k_mma<16, false>, cudaFuncAttributeMaxDynamicSharedMemorySize, SMEM_SZ);

    k_prep<<<PB_X + PB_W + PB_G, 256>>>(x, conv_w, gate_w);

    dim3 grid(DDIM / 128, MTOT / 128);   // (8, 120)
    k_mma<48, true><<<grid, 256, SMEM_SZ>>>(conv_b, nullptr);
    k_mma<16, false><<<grid, 256, SMEM_SZ>>>(gate_b, out);
}

// round 11
// speedup vs baseline: 1.4090x; 1.1032x over previous
#include <cuda_runtime.h>
#include <cuda_fp16.h>
#include <cstdint>
#include <cstddef>

// Problem: B=16, T=960, D=1024, W=10
#define DDIM  1024
#define WWIN  10
#define MTOT  15360          // B*T
#define KCONV 3072           // 3*D

static constexpr size_t XSZ = (size_t)MTOT * DDIM;
static constexpr size_t WSZ = (size_t)DDIM * KCONV;
static constexpr size_t GSZ = (size_t)DDIM * DDIM;

static constexpr int NTILE_M = MTOT / 128;   // 120
static constexpr int NTILE_N = DDIM / 128;   // 8
static constexpr int CONV_TILES = NTILE_M * NTILE_N;   // 960
static constexpr int ALL_TILES  = 2 * CONV_TILES;      // 1920
static constexpr int GRID_P     = 296;                 // 148 SMs x occ 2

// Device scratch (allocation-free rules; zero-initialized by CUDA)
__device__ __half  g_x1[XSZ];      // x fp16, [m][c]
__device__ __half  g_w1[WSZ];      // conv w fp16, [n][k=s*1024+c]
__device__ __half  g_g1[GSZ];      // gate w fp16, [e][d]
__device__ __half  g_c1[XSZ];      // cnn fp16, [m][d]
__device__ __align__(128) __half g_zero[64];   // 128B of zeros (masked conv taps)
__device__ int g_ticket;
__device__ int g_cnt[NTILE_M];     // conv tiles finished per m-block

// ------------------------------------------------------------------ PTX helpers
__device__ __forceinline__ uint32_t smem_u32(const void* p) {
    uint32_t a;
    asm("{ .reg .u64 t; cvta.to.shared.u64 t, %1; cvt.u32.u64 %0, t; }" : "=r"(a) : "l"(p));
    return a;
}
__device__ __forceinline__ void cpbulk(uint32_t dst, const void* src, uint32_t bytes,
                                       uint32_t mbar) {
    asm volatile(
        "cp.async.bulk.shared::cluster.global.mbarrier::complete_tx::bytes "
        "[%0], [%1], %2, [%3];"
        :: "r"(dst), "l"(src), "r"(bytes), "r"(mbar) : "memory");
}
__device__ __forceinline__ void mbar_init(uint32_t a, uint32_t cnt) {
    asm volatile("mbarrier.init.shared.b64 [%0], %1;" :: "r"(a), "r"(cnt) : "memory");
}
__device__ __forceinline__ void mbar_expect_tx(uint32_t a, uint32_t tx) {
    asm volatile("mbarrier.arrive.expect_tx.shared.b64 _, [%0], %1;"
                 :: "r"(a), "r"(tx) : "memory");
}
__device__ __forceinline__ void mbar_wait(uint32_t a, uint32_t ph) {
    uint32_t done = 0;
    while (!done) {
        asm volatile(
            "{\n\t.reg .pred p;\n\t"
            "mbarrier.try_wait.parity.acquire.cta.shared::cta.b64 p, [%1], %2, 0x989680;\n\t"
            "selp.b32 %0, 1, 0, p;\n\t}"
            : "=r"(done) : "r"(a), "r"(ph) : "memory");
    }
}
__device__ __forceinline__ void mbar_arrive(uint32_t a) {
    asm volatile("mbarrier.arrive.shared.b64 _, [%0];" :: "r"(a) : "memory");
}
__device__ __forceinline__ void ldsm4(uint32_t* r, uint32_t addr) {
    asm volatile("ldmatrix.sync.aligned.m8n8.x4.shared.b16 {%0,%1,%2,%3}, [%4];"
                 : "=r"(r[0]), "=r"(r[1]), "=r"(r[2]), "=r"(r[3]) : "r"(addr));
}
__device__ __forceinline__ void mma16816(float* d, const uint32_t* a, const uint32_t* b) {
    asm volatile("mma.sync.aligned.m16n8k16.row.col.f32.f16.f16.f32 "
                 "{%0,%1,%2,%3}, {%4,%5,%6,%7}, {%8,%9}, {%0,%1,%2,%3};"
                 : "+f"(d[0]), "+f"(d[1]), "+f"(d[2]), "+f"(d[3])
                 : "r"(a[0]), "r"(a[1]), "r"(a[2]), "r"(a[3]), "r"(b[0]), "r"(b[1]));
}
__device__ __forceinline__ uint32_t pack_h2(float a, float b) {
    return (uint32_t)__half_as_ushort(__float2half_rn(a)) |
           ((uint32_t)__half_as_ushort(__float2half_rn(b)) << 16);
}

// ------------------------------------------------------------------ preprocessing (merged)
static constexpr int PB_X = (int)(XSZ / 1024);
static constexpr int PB_W = (int)(WSZ / 256);
static constexpr int PB_G = (int)(GSZ / 1024);
__global__ void k_prep(const float* __restrict__ x, const float* __restrict__ cw,
                       const float* __restrict__ gw) {
    const int b = blockIdx.x;
    if (b == 0) {                         // reset scheduler state (replay-safe)
        if (threadIdx.x == 255) g_ticket = 0;
        if (threadIdx.x < NTILE_M) g_cnt[threadIdx.x] = 0;
    }
    if (b < PB_X) {
        size_t i = ((size_t)b * 256 + threadIdx.x) * 4;
        float4 v = *reinterpret_cast<const float4*>(x + i);
        uint2 u; u.x = pack_h2(v.x, v.y); u.y = pack_h2(v.z, v.w);
        *reinterpret_cast<uint2*>(g_x1 + i) = u;
    } else if (b < PB_X + PB_W) {
        size_t i = (size_t)(b - PB_X) * 256 + threadIdx.x;   // [n][k=s*1024+c]
        int n = (int)(i / KCONV);
        int k = (int)(i - (size_t)n * KCONV);
        int s = k >> 10, c = k & (DDIM - 1);
        g_w1[i] = __float2half_rn(cw[(size_t)n * KCONV + c * 3 + s]);
    } else {
        size_t i = ((size_t)(b - PB_X - PB_W) * 256 + threadIdx.x) * 4;
        float4 v = *reinterpret_cast<const float4*>(gw + i);
        uint2 u; u.x = pack_h2(v.x, v.y); u.y = pack_h2(v.z, v.w);
        *reinterpret_cast<uint2*>(g_g1 + i) = u;
    }
}

// ------------------------------------------------------------------ persistent GEMM
// CTA tile 128x128, BK=64 fp16, 144B row pitch (conflict-free ldsm, no swizzle),
// cp.async.bulk loads, 3-stage mbarrier ring keyed to per-CTA global chunk G.
// Persistent grid of 296 CTAs pulls tiles from a global ticket:
//   tiles [0,960)   = conv GEMM tiles   (writes g_c1, bumps g_cnt[mb])
//   tiles [960,1920)= gate GEMM tiles   (spins on g_cnt[mb]==8, writes out)
static constexpr int ROWB = 144;
static constexpr int PL_A = 0, PL_B = 128 * ROWB;        // 18432
static constexpr int STSZ = 2 * 128 * ROWB;              // 36864
static constexpr int MB_OFF = 3 * STSZ;                  // 110592
static constexpr int TID_OFF = MB_OFF + 56;              // tile-id broadcast slot
static constexpr int SMEM_SZ = MB_OFF + 64;              // 110656

__global__ __launch_bounds__(256, 2)
void k_mma(const float* __restrict__ conv_b, const float* __restrict__ gate_b,
           float* __restrict__ out) {
    extern __shared__ char smem[];
    const uint32_t sb = smem_u32(smem);
    const uint32_t mbF = sb + MB_OFF;        // full[3]
    const uint32_t mbE = sb + MB_OFF + 24;   // empty[3]

    const int tid = threadIdx.x;
    const int lane = tid & 31, w = tid >> 5;
    const int wm = w >> 1, wn = w & 1;       // warp grid 4(M) x 2(N)
    const int li = lane & 7, lg = lane >> 3;

    if (tid == 0) {
#pragma unroll
        for (int s = 0; s < 3; ++s) {
            mbar_init(mbF + s * 8, 256);     // per-thread expect_tx arrivals
            mbar_init(mbE + s * 8, 8);       // lane-0 of each warp
        }
    }
    __syncthreads();

    const bool isA = (tid < 128);
    const int row = isA ? tid : (tid - 128);

    uint32_t G = 0;                          // per-CTA global chunk counter

    for (;;) {
        __syncthreads();                     // protect TID_OFF reuse
        if (tid == 0) *reinterpret_cast<int*>(smem + TID_OFF) = atomicAdd(&g_ticket, 1);
        __syncthreads();
        const int t = *reinterpret_cast<int*>(smem + TID_OFF);
        if (t >= ALL_TILES) break;

        const bool conv = (t < CONV_TILES);
        const int tt = conv ? t : (t - CONV_TILES);
        const int n0 = (tt & 7) * 128;
        const int m0 = (tt >> 3) * 128;
        const int CH = conv ? 48 : 16;
        const int amw = (m0 + row) % WWIN;

        if (!conv) {                         // wait for cnn rows of this m-block
            if (tid == 0) {
                while (atomicAdd(&g_cnt[tt >> 3], 0) < NTILE_N) __nanosleep(64);
            }
            __syncthreads();
            __threadfence();
        }

        auto load_stage = [&](int c, uint32_t gg) {
            const uint32_t st = gg % 3, u = gg / 3;
            if (u > 0) mbar_wait(mbE + st * 8, (u - 1) & 1);
            const uint32_t base = sb + st * STSZ;
            const void* src;
            if (isA) {
                if (conv) {
                    const int s = c >> 4, dt = s - 1, kc = (c & 15) << 6;
                    const bool valid = ((unsigned)(amw + dt)) < (unsigned)WWIN;
                    src = valid ? (const void*)(g_x1 + (size_t)(m0 + row + dt) * DDIM + kc)
                                : (const void*)g_zero;
                } else {
                    src = g_c1 + (size_t)(m0 + row) * DDIM + (c << 6);
                }
            } else {
                src = conv ? (const void*)(g_w1 + (size_t)(n0 + row) * KCONV + (c << 6))
                           : (const void*)(g_g1 + (size_t)(n0 + row) * DDIM + (c << 6));
            }
            const uint32_t dst = base + (isA ? PL_A : PL_B) + row * ROWB;
            mbar_expect_tx(mbF + st * 8, 128);
            cpbulk(dst, src, 128, mbF + st * 8);
        };

        // prologue: 3 stages ahead
#pragma unroll
        for (int p = 0; p < 3; ++p) load_stage(p, G + p);

        float acc[2][8][4];
#pragma unroll
        for (int i = 0; i < 2; ++i)
#pragma unroll
            for (int j = 0; j < 8; ++j)
#pragma unroll
                for (int q = 0; q < 4; ++q) acc[i][j][q] = 0.f;

        for (int j = 0; j < CH; ++j) {
            const uint32_t gg = G + j;
            const uint32_t st = gg % 3;
            mbar_wait(mbF + st * 8, (gg / 3) & 1);
            const uint32_t bb = sb + st * STSZ;
#pragma unroll
            for (int ks = 0; ks < 4; ++ks) {
                uint32_t Bf[4][4];
#pragma unroll
                for (int nt2 = 0; nt2 < 4; ++nt2) {
                    const int br = wn * 64 + nt2 * 16 + li + (lg >> 1) * 8;
                    ldsm4(Bf[nt2], bb + PL_B + br * ROWB + (ks * 2 + (lg & 1)) * 16);
                }
#pragma unroll
                for (int mt = 0; mt < 2; ++mt) {
                    const int ar = wm * 32 + mt * 16 + li + (lg & 1) * 8;
                    uint32_t Af[4];
                    ldsm4(Af, bb + PL_A + ar * ROWB + (ks * 2 + (lg >> 1)) * 16);
#pragma unroll
                    for (int nt = 0; nt < 8; ++nt) {
                        const uint32_t b2[2] = {Bf[nt >> 1][(nt & 1) * 2],
                                                Bf[nt >> 1][(nt & 1) * 2 + 1]};
                        mma16816(acc[mt][nt], Af, b2);
                    }
                }
            }
            if (lane == 0) mbar_arrive(mbE + st * 8);
            if (j + 3 < CH) load_stage(j + 3, gg + 3);
        }
        G += CH;

        // ---- epilogue
        const float* bias = conv ? conv_b : gate_b;
#pragma unroll
        for (int mt = 0; mt < 2; ++mt) {
#pragma unroll
            for (int nt = 0; nt < 8; ++nt) {
                const int gn = n0 + wn * 64 + nt * 8 + (lane & 3) * 2;
                const float b0 = bias[gn], b1 = bias[gn + 1];
#pragma unroll
                for (int hh = 0; hh < 2; ++hh) {
                    const int gm = m0 + wm * 32 + mt * 16 + (lane >> 2) + hh * 8;
                    float v0 = acc[mt][nt][hh * 2 + 0] + b0;
                    float v1 = acc[mt][nt][hh * 2 + 1] + b1;
                    const size_t off = (size_t)gm * DDIM + gn;
                    if (conv) {
                        *reinterpret_cast<uint32_t*>(g_c1 + off) = pack_h2(v0, v1);
                    } else {
                        const __half2 ch = *reinterpret_cast<const __half2*>(g_c1 + off);
                        const float2 cv = __half22float2(ch);
                        float2 o;
                        o.x = cv.x * (1.f / (1.f + __expf(-v0)));
                        o.y = cv.y * (1.f / (1.f + __expf(-v1)));
                        *reinterpret_cast<float2*>(out + off) = o;
                    }
                }
            }
        }
        if (conv) {                          // publish this m-block's conv tile
            __threadfence();
            __syncthreads();
            if (tid == 0) atomicAdd(&g_cnt[tt >> 3], 1);
        }
    }
}

// ------------------------------------------------------------------ launch
extern "C" void kernel_launch(void* const* d_in, const int* in_sizes, int n_in,
                              void* d_out, int out_size) {
    const float* x      = (const float*)d_in[0];
    const float* conv_w = (const float*)d_in[1];
    const float* conv_b = (const float*)d_in[2];
    const float* gate_w = (const float*)d_in[3];
    const float* gate_b = (const float*)d_in[4];
    float* out = (float*)d_out;

    cudaFuncSetAttribute(k_mma, cudaFuncAttributeMaxDynamicSharedMemorySize, SMEM_SZ);

    k_prep<<<PB_X + PB_W + PB_G, 256>>>(x, conv_w, gate_w);
    k_mma<<<GRID_P, 256, SMEM_SZ>>>(conv_b, gate_b, out);
}